// round 16
// baseline (speedup 1.0000x reference)
#include <cuda_runtime.h>
#include <cuda_fp16.h>
#include <cuda_bf16.h>
#include <cstdint>

#define BATCH 8192
#define NDIM  1024
#define MDIM  8192
#define MHALF 4096

#define STG1      24576   // gemm1 stage: A(8K) + B hi|lo interleaved (16K); 4 stages = 96KB
#define STG1S     40960   // syrk stage (2 stages = 80KB, within the 96KB alloc)
#define NSTG2     4
#define STG2      25600   // gemm2 stage: A(8K) B(16K) scl(1K) + pad

// ---------------- scratch ----------------------------------------------------
__device__ float  g_Wq     [(size_t)NDIM * MHALF];   // raw quantized weights [n][j]
__device__ __half g_WqThi16[(size_t)MHALF * NDIM];   // fp16 hi of 2048*Wq, [j][n]
__device__ __half g_WqTlo16[(size_t)MHALF * NDIM];   // fp16 lo of 2048*Wq, [j][n]
__device__ __half g_Wv16   [(size_t)NDIM * MHALF];   // fp16(21*q) integer weights [n][j]
__device__ float  g_sclT   [(size_t)(MHALF / 32) * NDIM]; // s/21 per (jblk, n); *amax_h later
__device__ float  g_Wc     [(size_t)NDIM * MHALF];   // tf32(Wc) [n][j]
__device__ float  g_G      [(size_t)NDIM * NDIM];    // tf32(Wc @ Wc^T)
__device__ __half g_xq16   [(size_t)BATCH * NDIM];   // int-valued quantized x (fp16)
__device__ float  g_xc     [(size_t)BATCH * NDIM];   // tf32(x)
__device__ float  g_H      [(size_t)BATCH * MHALF];  // H_exp raw fp32
__device__ __half g_Hq16   [(size_t)BATCH * MHALF];  // int-valued quantized H_exp (fp16)
__device__ int    g_amax[2];

// ---------------- helpers ----------------------------------------------------
__device__ __forceinline__ float to_tf32(float x) {
    float r; asm("cvt.rna.tf32.f32 %0, %1;" : "=f"(r) : "f"(x)); return r;
}
__device__ __forceinline__ uint32_t smem_u32(const void* p) {
    uint32_t a;
    asm("{ .reg .u64 t; cvta.to.shared.u64 t, %1; cvt.u32.u64 %0, t; }" : "=r"(a) : "l"(p));
    return a;
}
__device__ __forceinline__ void cp16(uint32_t d, const void* s) {
    asm volatile("cp.async.cg.shared.global [%0], [%1], 16;" :: "r"(d), "l"(s));
}
__device__ __forceinline__ void cp_commit() {
    asm volatile("cp.async.commit_group;" ::: "memory");
}
template<int N> __device__ __forceinline__ void cp_wait() {
    asm volatile("cp.async.wait_group %0;" :: "n"(N) : "memory");
}
__device__ __forceinline__ void mma_tf32(float* d, const uint32_t* a, uint32_t b0, uint32_t b1) {
    asm volatile(
        "mma.sync.aligned.m16n8k8.row.col.f32.tf32.tf32.f32 "
        "{%0,%1,%2,%3},{%4,%5,%6,%7},{%8,%9},{%0,%1,%2,%3};"
        : "+f"(d[0]), "+f"(d[1]), "+f"(d[2]), "+f"(d[3])
        : "r"(a[0]), "r"(a[1]), "r"(a[2]), "r"(a[3]), "r"(b0), "r"(b1));
}
__device__ __forceinline__ void mma_f16(float* d, const uint32_t* a, uint32_t b0, uint32_t b1) {
    asm volatile(
        "mma.sync.aligned.m16n8k16.row.col.f32.f16.f16.f32 "
        "{%0,%1,%2,%3},{%4,%5,%6,%7},{%8,%9},{%0,%1,%2,%3};"
        : "+f"(d[0]), "+f"(d[1]), "+f"(d[2]), "+f"(d[3])
        : "r"(a[0]), "r"(a[1]), "r"(a[2]), "r"(a[3]), "r"(b0), "r"(b1));
}
// D = A*B + 0  (fresh accumulator)
__device__ __forceinline__ void mma_f16_init(float* d, const uint32_t* a, uint32_t b0, uint32_t b1) {
    asm volatile(
        "mma.sync.aligned.m16n8k16.row.col.f32.f16.f16.f32 "
        "{%0,%1,%2,%3},{%4,%5,%6,%7},{%8,%9},{%10,%10,%10,%10};"
        : "=f"(d[0]), "=f"(d[1]), "=f"(d[2]), "=f"(d[3])
        : "r"(a[0]), "r"(a[1]), "r"(a[2]), "r"(a[3]), "r"(b0), "r"(b1), "f"(0.0f));
}
__device__ __forceinline__ void ldsm4(uint32_t* r, uint32_t addr) {
    asm volatile("ldmatrix.sync.aligned.m8n8.x4.shared.b16 {%0,%1,%2,%3}, [%4];"
        : "=r"(r[0]), "=r"(r[1]), "=r"(r[2]), "=r"(r[3]) : "r"(addr));
}
__device__ __forceinline__ void ldsm2(uint32_t& r0, uint32_t& r1, uint32_t addr) {
    asm volatile("ldmatrix.sync.aligned.m8n8.x2.shared.b16 {%0,%1}, [%2];"
        : "=r"(r0), "=r"(r1) : "r"(addr));
}

// ---------------- prep kernels ----------------------------------------------
__global__ void reset_kernel() { g_amax[0] = 0; g_amax[1] = 0; }

#define P1_QW 16384
#define P1_GW 16384
#define P1_AM 1024
__global__ void prep1_kernel(const float4* __restrict__ x4,
                             const float* __restrict__ W,
                             const int* __restrict__ idx,
                             const int* __restrict__ idxc) {
    int bid = blockIdx.x;
    if (bid < P1_QW) {
        int gw   = (bid * 256 + (int)threadIdx.x) >> 5;
        int lane = threadIdx.x & 31;
        int flat = gw * 32 + lane;
        int n = flat >> 12;
        int j = flat & (MHALF - 1);
        float w = W[(size_t)n * MDIM + idx[j]];

        float s = fabsf(w);
        #pragma unroll
        for (int o = 16; o; o >>= 1) s = fmaxf(s, __shfl_xor_sync(0xffffffffu, s, o));
        s = fmaxf(s, 1e-8f);

        float nb  = w / s;
        float anb = fabsf(nb);

        float v1 = anb; int i1 = lane;
        #pragma unroll
        for (int o = 16; o; o >>= 1) {
            float ov = __shfl_xor_sync(0xffffffffu, v1, o);
            int   oi = __shfl_xor_sync(0xffffffffu, i1, o);
            if (ov > v1 || (ov == v1 && oi < i1)) { v1 = ov; i1 = oi; }
        }
        float m2 = (lane == i1) ? -1.0f : anb;
        float v2 = m2; int i2 = lane;
        #pragma unroll
        for (int o = 16; o; o >>= 1) {
            float ov = __shfl_xor_sync(0xffffffffu, v2, o);
            int   oi = __shfl_xor_sync(0xffffffffu, i2, o);
            if (ov > v2 || (ov == v2 && oi < i2)) { v2 = ov; i2 = oi; }
        }
        bool top = (lane == i1) || (lane == i2);

        float q4  = rintf(nb * 7.0f) / 7.0f;
        float sgn = (nb > 0.0f) ? 1.0f : ((nb < 0.0f) ? -1.0f : 0.0f);
        float q2  = sgn * ((anb > 0.66f) ? 1.0f : (1.0f / 3.0f));
        g_Wq[flat] = (top ? q4 : q2) * s;

        float v21 = top ? 3.0f * rintf(nb * 7.0f)
                        : sgn * ((anb > 0.66f) ? 21.0f : 7.0f);
        g_Wv16[flat] = __float2half_rn(v21);
        if (lane == 0) g_sclT[(size_t)(j >> 5) * NDIM + n] = s * (1.0f / 21.0f);
    } else if (bid < P1_QW + P1_GW) {
        int t = (bid - P1_QW) * 256 + threadIdx.x;
        int n = t >> 12;
        int j = t & (MHALF - 1);
        g_Wc[t] = to_tf32(W[(size_t)n * MDIM + idxc[j]]);
    } else {
        __shared__ float sm[256];
        int lb = bid - P1_QW - P1_GW;
        const long n4 = (long)BATCH * NDIM / 4;
        float m = 0.0f;
        for (long i = (long)lb * 256 + threadIdx.x; i < n4; i += (long)P1_AM * 256) {
            float4 v = x4[i];
            m = fmaxf(m, fmaxf(fmaxf(fabsf(v.x), fabsf(v.y)), fmaxf(fabsf(v.z), fabsf(v.w))));
        }
        sm[threadIdx.x] = m;
        __syncthreads();
        #pragma unroll
        for (int s = 128; s; s >>= 1) {
            if (threadIdx.x < s) sm[threadIdx.x] = fmaxf(sm[threadIdx.x], sm[threadIdx.x + s]);
            __syncthreads();
        }
        if (threadIdx.x == 0) atomicMax(&g_amax[0], __float_as_int(sm[0]));
    }
}

#define P2_TR 4096
__global__ void prep2_kernel(const float4* __restrict__ x4) {
    int bid = blockIdx.x;
    if (bid < P2_TR) {
        __shared__ float t[32][33];
        int j0 = (bid & 127) * 32, n0 = (bid >> 7) * 32;
        int tx = threadIdx.x & 31, ty = threadIdx.x >> 5;
        #pragma unroll
        for (int s = 0; s < 32; s += 8)
            t[ty + s][tx] = g_Wq[(size_t)(n0 + ty + s) * MHALF + j0 + tx];
        __syncthreads();
        #pragma unroll
        for (int s = 0; s < 32; s += 8) {
            float v = t[tx][ty + s] * 2048.0f;
            __half h = __float2half_rn(v);
            __half l = __float2half_rn(v - __half2float(h));
            size_t o = (size_t)(j0 + ty + s) * NDIM + n0 + tx;
            g_WqThi16[o] = h;
            g_WqTlo16[o] = l;
        }
    } else {
        int t = (bid - P2_TR) * 256 + threadIdx.x;
        float sc = 127.0f / fmaxf(__int_as_float(g_amax[0]), 1e-8f);
        float4 v = x4[t];
        float q0 = fminf(fmaxf(rintf(v.x * sc), -128.0f), 127.0f);
        float q1 = fminf(fmaxf(rintf(v.y * sc), -128.0f), 127.0f);
        float q2 = fminf(fmaxf(rintf(v.z * sc), -128.0f), 127.0f);
        float q3 = fminf(fmaxf(rintf(v.w * sc), -128.0f), 127.0f);
        __half h[4] = { __float2half_rn(q0), __float2half_rn(q1),
                        __float2half_rn(q2), __float2half_rn(q3) };
        *(uint2*)&g_xq16[(size_t)t * 4] = *(uint2*)h;
        float4 c = make_float4(to_tf32(v.x), to_tf32(v.y), to_tf32(v.z), to_tf32(v.w));
        *(float4*)&g_xc[(size_t)t * 4] = c;
    }
}

// quantize H_exp -> integer-valued fp16; tail blocks fold amax_h into g_sclT
__global__ void quant_h_kernel() {
    const int NBQ = BATCH * MHALF / 4 / 256;   // 32768
    int bid = blockIdx.x;
    float ah127 = fmaxf(__int_as_float(g_amax[1]), 1e-8f);
    if (bid >= NBQ) {
        int t = (bid - NBQ) * 256 + threadIdx.x;
        float f = ah127 * (1.0f / 127.0f);
        float4 v = *(const float4*)&g_sclT[(size_t)t * 4];
        v.x *= f; v.y *= f; v.z *= f; v.w *= f;
        *(float4*)&g_sclT[(size_t)t * 4] = v;
        return;
    }
    int t = bid * 256 + threadIdx.x;
    float sh = 127.0f / ah127;
    float4 v = *(const float4*)&g_H[(size_t)t * 4];
    __half h[4];
    h[0] = __float2half_rn(fminf(fmaxf(rintf(v.x * sh), -128.0f), 127.0f));
    h[1] = __float2half_rn(fminf(fmaxf(rintf(v.y * sh), -128.0f), 127.0f));
    h[2] = __float2half_rn(fminf(fmaxf(rintf(v.z * sh), -128.0f), 127.0f));
    h[3] = __float2half_rn(fminf(fmaxf(rintf(v.w * sh), -128.0f), 127.0f));
    *(uint2*)&g_Hq16[(size_t)t * 4] = *(uint2*)h;
}

// ---------------- GEMM1 + fused symmetric SYRK (64x128 tiles, occ 2) ---------
// GEMM1 path: K-chunk 32, 4 stages x 24KB, single sync per chunk.
//   stage: [0,8K) A 64rows x 128B (granules 0..3 = k0..31)
//          [8K,24K) B 128rows x 128B (granules 0..3 = hi k0..31, 4..7 = lo k0..31)
// SYRK path: unchanged 2-stage x 40KB (fits in the same 96KB window).
#define NSYRK 72
__global__ void __launch_bounds__(256, 2) gemm1_kernel() {
    extern __shared__ char smem[];
    const int tid = threadIdx.x, wid = tid >> 5, lane = tid & 31;
    const int wm0 = (wid & 1) * 32, wn0 = (wid >> 1) * 32;
    const uint32_t sbase = smem_u32(smem);
    const int bid = blockIdx.x;

    const int l7 = lane & 7;
    const int lh = (lane >> 3) & 1;
    const int lq = (lane >> 4) & 1;
    const int l2 = lane >> 3;
    uint32_t arow[2];
    #pragma unroll
    for (int i = 0; i < 2; i++)
        arow[i] = (uint32_t)((wm0 + i * 16 + l7 + 8 * lh) * 128);

    if (bid < NSYRK) {
        // ---- symmetric SYRK (tf32, K-chunk 32, 2-stage) ----
        int off = bid, tj = 0;
        while (off >= 2 * tj + 2) { off -= 2 * tj + 2; tj++; }
        const int ti = off;
        const int m0 = ti * 64, n0 = tj * 128;
        const int NCH = MHALF / 32;   // 128
        uint32_t brow[4];
        #pragma unroll
        for (int j = 0; j < 4; j++)
            brow[j] = (uint32_t)(8192 + (wn0 + j * 8 + l7) * 128);

        auto issue = [&](int c) {
            const int k0 = c * 32;
            const uint32_t st = sbase + (uint32_t)(c & 1) * STG1S;
            #pragma unroll
            for (int p = 0; p < 2; p++) {
                int l = tid + p * 256;
                int r = l >> 3, gc = l & 7;
                cp16(st + (uint32_t)(r * 128 + ((gc ^ (r & 7)) << 4)),
                     g_Wc + (size_t)(m0 + r) * MHALF + k0 + gc * 4);
            }
            #pragma unroll
            for (int p = 0; p < 4; p++) {
                int l = tid + p * 256;
                int r = l >> 3, gc = l & 7;
                cp16(st + 8192u + (uint32_t)(r * 128 + ((gc ^ (r & 7)) << 4)),
                     g_Wc + (size_t)(n0 + r) * MHALF + k0 + gc * 4);
            }
            cp_commit();
        };
        issue(0); issue(1);

        float acc[2][4][4] = {};
        for (int c = 0; c < NCH; c++) {
            cp_wait<1>();
            __syncthreads();
            const uint32_t st = sbase + (uint32_t)(c & 1) * STG1S;
            #pragma unroll
            for (int ks = 0; ks < 4; ks++) {
                uint32_t a[2][4];
                #pragma unroll
                for (int i = 0; i < 2; i++)
                    ldsm4(a[i], st + arow[i] + (uint32_t)((((ks << 1) | lq) ^ l7) << 4));
                #pragma unroll
                for (int j = 0; j < 4; j++) {
                    uint32_t b0, b1;
                    ldsm2(b0, b1, st + brow[j] + (uint32_t)((((ks << 1) | lh) ^ l7) << 4));
                    #pragma unroll
                    for (int i = 0; i < 2; i++) mma_tf32(acc[i][j], a[i], b0, b1);
                }
            }
            __syncthreads();
            if (c + 2 < NCH) issue(c + 2); else cp_commit();
        }
        const int g = lane >> 2, tig = lane & 3;
        #pragma unroll
        for (int i = 0; i < 2; i++)
            #pragma unroll
            for (int j = 0; j < 4; j++) {
                int r   = m0 + wm0 + i * 16 + g;
                int col = n0 + wn0 + j * 8 + tig * 2;
                int tjs = 2 * tj + ((wn0 + j * 8) >= 64 ? 1 : 0);
                float v0 = to_tf32(acc[i][j][0]), v1 = to_tf32(acc[i][j][1]);
                float v2 = to_tf32(acc[i][j][2]), v3 = to_tf32(acc[i][j][3]);
                if (ti <= tjs) {
                    *(float2*)&g_G[(size_t)r * NDIM + col]       = make_float2(v0, v1);
                    *(float2*)&g_G[(size_t)(r + 8) * NDIM + col] = make_float2(v2, v3);
                }
                if (ti < tjs) {
                    g_G[(size_t)col * NDIM + r]           = v0;
                    g_G[(size_t)(col + 1) * NDIM + r]     = v1;
                    g_G[(size_t)col * NDIM + r + 8]       = v2;
                    g_G[(size_t)(col + 1) * NDIM + r + 8] = v3;
                }
            }
        return;
    }

    // ---- GEMM1 path (fp16 2-term split, 64x128, K-chunk 32, 4-stage) ----
    const int t = bid - NSYRK;
    const int n0 = (t & 31) * 128, row0 = (t >> 5) * 64;
    const int NCH = NDIM / 32;   // 32
    const int bgsel = (l2 & 1) + ((l2 >> 1) << 2);   // B granule base per lane-quarter
    uint32_t brow[4];
    #pragma unroll
    for (int j = 0; j < 4; j++)
        brow[j] = (uint32_t)(8192 + (wn0 + j * 8 + l7) * 128);

    auto issue = [&](int c) {
        const int k0 = c * 32;
        const uint32_t st = sbase + (uint32_t)(c & 3) * STG1;
        // A: 64 rows x 4 granules (one pass)
        {
            int r = tid >> 2, gc = tid & 3;
            cp16(st + (uint32_t)(r * 128 + ((gc ^ (r & 7)) << 4)),
                 g_xq16 + (size_t)(row0 + r) * NDIM + k0 + gc * 8);
        }
        // B: 128 rows x 8 granules (hi 0..3 | lo 4..7), 4 passes
        #pragma unroll
        for (int p = 0; p < 4; p++) {
            int l = tid + p * 256;
            int r = l >> 3, gc = l & 7;
            const __half* src = (gc < 4)
                ? g_WqThi16 + (size_t)(n0 + r) * NDIM + k0 + (gc & 3) * 8
                : g_WqTlo16 + (size_t)(n0 + r) * NDIM + k0 + (gc & 3) * 8;
            cp16(st + 8192u + (uint32_t)(r * 128 + ((gc ^ (r & 7)) << 4)), src);
        }
        cp_commit();
    };

    issue(0); issue(1); issue(2);

    float acc[2][4][4] = {};

    for (int c = 0; c < NCH; c++) {
        cp_wait<2>();
        __syncthreads();
        if (c + 3 < NCH) issue(c + 3); else cp_commit();

        const uint32_t st = sbase + (uint32_t)(c & 3) * STG1;
        #pragma unroll
        for (int s = 0; s < 2; s++) {
            uint32_t a[2][4];
            #pragma unroll
            for (int i = 0; i < 2; i++)
                ldsm4(a[i], st + arow[i] + (uint32_t)((((s << 1) | lq) ^ l7) << 4));
            #pragma unroll
            for (int j = 0; j < 4; j++) {
                uint32_t b[4];
                ldsm4(b, st + brow[j] + (uint32_t)(((2 * s + bgsel) ^ l7) << 4));
                #pragma unroll
                for (int i = 0; i < 2; i++) mma_f16(acc[i][j], a[i], b[0], b[1]);
                #pragma unroll
                for (int i = 0; i < 2; i++) mma_f16(acc[i][j], a[i], b[2], b[3]);
            }
        }
    }

    const int g = lane >> 2, tig = lane & 3;
    float lmax = 0.0f;
    const float inv = fmaxf(__int_as_float(g_amax[0]), 1e-8f) * (1.0f / (127.0f * 2048.0f));
    #pragma unroll
    for (int i = 0; i < 2; i++) {
        #pragma unroll
        for (int j = 0; j < 4; j++) {
            int r   = row0 + wm0 + i * 16 + g;
            int col = n0 + wn0 + j * 8 + tig * 2;
            float v0 = acc[i][j][0] * inv, v1 = acc[i][j][1] * inv;
            float v2 = acc[i][j][2] * inv, v3 = acc[i][j][3] * inv;
            lmax = fmaxf(lmax, fmaxf(fmaxf(fabsf(v0), fabsf(v1)),
                                     fmaxf(fabsf(v2), fabsf(v3))));
            *(float2*)&g_H[(size_t)r * MHALF + col]       = make_float2(v0, v1);
            *(float2*)&g_H[(size_t)(r + 8) * MHALF + col] = make_float2(v2, v3);
        }
    }

    float* red = (float*)smem;
    __syncthreads();
    red[tid] = lmax;
    __syncthreads();
    #pragma unroll
    for (int s = 128; s; s >>= 1) {
        if (tid < s) red[tid] = fmaxf(red[tid], red[tid + s]);
        __syncthreads();
    }
    if (tid == 0) atomicMax(&g_amax[1], __float_as_int(red[0]));
}

// ---------------- GEMM2: out = relu(Hq@Wq^T + x@G + b) -----------------------
// 64x128 tiles (occ 2), ldmatrix inner loops.
__global__ void __launch_bounds__(256, 2) gemm2_kernel(float* __restrict__ outp,
                                                       const float* __restrict__ biasp) {
    extern __shared__ char smem[];
    const int tid = threadIdx.x, wid = tid >> 5, lane = tid & 31;
    const int wm0 = (wid & 1) * 32, wn0 = (wid >> 1) * 32;
    const int n0 = blockIdx.x * 128, row0 = blockIdx.y * 64;
    const uint32_t sbase = smem_u32(smem);
    const int NCH = 64 + NDIM / 32;   // 96

    const int l7 = lane & 7;
    const int lh = (lane >> 3) & 1;
    const int lq = (lane >> 4) & 1;
    const int l2 = lane >> 3;
    uint32_t arow[2];
    #pragma unroll
    for (int i = 0; i < 2; i++)
        arow[i] = (uint32_t)((wm0 + i * 16 + l7 + 8 * lh) * 128);
    uint32_t brow[4];
    #pragma unroll
    for (int j = 0; j < 4; j++)
        brow[j] = (uint32_t)(8192 + (wn0 + j * 8 + l7) * 128);

    auto issue = [&](int c) {
        const uint32_t st = sbase + (uint32_t)(c & 3) * STG2;
        if (c < 64) {
            const int k0 = c * 64;
            #pragma unroll
            for (int p = 0; p < 2; p++) {
                int l = tid + p * 256;
                int r = l >> 3, gc = l & 7;
                cp16(st + (uint32_t)(r * 128 + ((gc ^ (r & 7)) << 4)),
                     g_Hq16 + (size_t)(row0 + r) * MHALF + k0 + gc * 8);
            }
            #pragma unroll
            for (int p = 0; p < 4; p++) {
                int l = tid + p * 256;
                int r = l >> 3, gc = l & 7;
                cp16(st + 8192u + (uint32_t)(r * 128 + ((gc ^ (r & 7)) << 4)),
                     g_Wv16 + (size_t)(n0 + r) * MHALF + k0 + gc * 8);
            }
            if (tid < 64) {
                int bb = tid >> 5, o = (tid & 31) * 4;
                cp16(st + 24576u + (uint32_t)(bb * 512 + o * 4),
                     g_sclT + (size_t)((k0 >> 5) + bb) * NDIM + n0 + o);
            }
        } else {
            const int k0 = (c - 64) * 32;
            #pragma unroll
            for (int p = 0; p < 2; p++) {
                int l = tid + p * 256;
                int r = l >> 3, gc = l & 7;
                cp16(st + (uint32_t)(r * 128 + ((gc ^ (r & 7)) << 4)),
                     g_xc + (size_t)(row0 + r) * NDIM + k0 + gc * 4);
            }
            #pragma unroll
            for (int p = 0; p < 4; p++) {
                int l = tid + p * 256;
                int r = l >> 3, gc = l & 7;
                cp16(st + 8192u + (uint32_t)(r * 128 + ((gc ^ (r & 7)) << 4)),
                     g_G + (size_t)(n0 + r) * NDIM + k0 + gc * 4);
            }
        }
        cp_commit();
    };

    issue(0); issue(1); issue(2);

    float accf[2][4][4] = {};

    for (int c = 0; c < NCH; c++) {
        cp_wait<2>();
        __syncthreads();
        if (c + 3 < NCH) issue(c + 3); else cp_commit();

        const uint32_t st = sbase + (uint32_t)(c & 3) * STG2;
        if (c < 64) {
            const float* sScl = (const float*)(smem + (c & 3) * STG2 + 24576);
            #pragma unroll
            for (int b32 = 0; b32 < 2; b32++) {
                uint32_t a[2][2][4];
                #pragma unroll
                for (int s16 = 0; s16 < 2; s16++)
                    #pragma unroll
                    for (int i = 0; i < 2; i++)
                        ldsm4(a[s16][i], st + arow[i] +
                              (uint32_t)(((b32 * 4 + s16 * 2 + lq) ^ l7) << 4));
                #pragma unroll
                for (int j = 0; j < 4; j++) {
                    uint32_t b[4];
                    ldsm4(b, st + brow[j] + (uint32_t)(((b32 * 4 + l2) ^ l7) << 4));
                    float acct[2][4];
                    #pragma unroll
                    for (int i = 0; i < 2; i++) mma_f16_init(acct[i], a[0][i], b[0], b[1]);
                    #pragma unroll
                    for (int i = 0; i < 2; i++) mma_f16(acct[i], a[1][i], b[2], b[3]);
                    float2 sc = *(const float2*)(sScl + b32 * 128 + wn0 + j * 8 + (lane & 3) * 2);
                    #pragma unroll
                    for (int i = 0; i < 2; i++) {
                        accf[i][j][0] += sc.x * acct[i][0];
                        accf[i][j][1] += sc.y * acct[i][1];
                        accf[i][j][2] += sc.x * acct[i][2];
                        accf[i][j][3] += sc.y * acct[i][3];
                    }
                }
            }
        } else {
            #pragma unroll
            for (int ks = 0; ks < 4; ks++) {
                uint32_t a[2][4];
                #pragma unroll
                for (int i = 0; i < 2; i++)
                    ldsm4(a[i], st + arow[i] + (uint32_t)((((ks << 1) | lq) ^ l7) << 4));
                #pragma unroll
                for (int j = 0; j < 4; j++) {
                    uint32_t b0, b1;
                    ldsm2(b0, b1, st + brow[j] + (uint32_t)((((ks << 1) | lh) ^ l7) << 4));
                    #pragma unroll
                    for (int i = 0; i < 2; i++) mma_tf32(accf[i][j], a[i], b0, b1);
                }
            }
        }
    }

    const int g = lane >> 2, tig = lane & 3;
    #pragma unroll
    for (int i = 0; i < 2; i++) {
        #pragma unroll
        for (int j = 0; j < 4; j++) {
            int r   = row0 + wm0 + i * 16 + g;
            int col = n0 + wn0 + j * 8 + tig * 2;
            float b0 = biasp[col], b1 = biasp[col + 1];
            float v0 = fmaxf(accf[i][j][0] + b0, 0.0f);
            float v1 = fmaxf(accf[i][j][1] + b1, 0.0f);
            float v2 = fmaxf(accf[i][j][2] + b0, 0.0f);
            float v3 = fmaxf(accf[i][j][3] + b1, 0.0f);
            *(float2*)&outp[(size_t)r * NDIM + col]       = make_float2(v0, v1);
            *(float2*)&outp[(size_t)(r + 8) * NDIM + col] = make_float2(v2, v3);
        }
    }
}

// ---------------- launcher ---------------------------------------------------
extern "C" void kernel_launch(void* const* d_in, const int* in_sizes, int n_in,
                              void* d_out, int out_size) {
    const float* x    = (const float*)d_in[0];
    const float* W    = (const float*)d_in[1];
    const float* b    = (const float*)d_in[2];
    const int*   idx  = (const int*)d_in[3];
    const int*   idxc = (const int*)d_in[4];
    float* out = (float*)d_out;

    const int SMEM1 = 4 * STG1;          // 96KB, occ 2
    const int SMEM2 = NSTG2 * STG2;      // 100KB, occ 2
    cudaFuncSetAttribute(gemm1_kernel, cudaFuncAttributeMaxDynamicSharedMemorySize, SMEM1);
    cudaFuncSetAttribute(gemm2_kernel, cudaFuncAttributeMaxDynamicSharedMemorySize, SMEM2);

    reset_kernel<<<1, 32>>>();
    prep1_kernel<<<P1_QW + P1_GW + P1_AM, 256>>>((const float4*)x, W, idx, idxc);
    prep2_kernel<<<P2_TR + BATCH * NDIM / 4 / 256, 256>>>((const float4*)x);

    gemm1_kernel<<<NSYRK + (MHALF / 128) * (BATCH / 64), 256, SMEM1>>>();

    quant_h_kernel<<<BATCH * MHALF / 4 / 256 + 128, 256>>>();

    gemm2_kernel<<<dim3(NDIM / 128, BATCH / 64), 256, SMEM2>>>(out, b);
}

// round 17
// speedup vs baseline: 1.0425x; 1.0425x over previous
#include <cuda_runtime.h>
#include <cuda_fp16.h>
#include <cuda_bf16.h>
#include <cstdint>

#define BATCH 8192
#define NDIM  1024
#define MDIM  8192
#define MHALF 4096

#define STG1      40960   // gemm1/syrk stage: A(8K) Bh(16K) Bl(16K); 2 stages -> 80KB, occ 2
#define NSTG2     4
#define STG2      25600   // gemm2 stage: A(8K) B(16K) scl(1K) + pad

// ---------------- scratch ----------------------------------------------------
__device__ float  g_Wq     [(size_t)NDIM * MHALF];   // raw quantized weights [n][j]
__device__ __half g_WqThi16[(size_t)MHALF * NDIM];   // fp16 hi of 2048*Wq, [j][n]
__device__ __half g_WqTlo16[(size_t)MHALF * NDIM];   // fp16 lo of 2048*Wq, [j][n]
__device__ __half g_Wv16   [(size_t)NDIM * MHALF];   // fp16(21*q) integer weights [n][j]
__device__ float  g_sclT   [(size_t)(MHALF / 32) * NDIM]; // s/21 per (jblk, n); *amax_h later
__device__ float  g_Wc     [(size_t)NDIM * MHALF];   // tf32(Wc) [n][j]
__device__ float  g_G      [(size_t)NDIM * NDIM];    // tf32(Wc @ Wc^T)
__device__ __half g_xq16   [(size_t)BATCH * NDIM];   // int-valued quantized x (fp16)
__device__ float  g_xc     [(size_t)BATCH * NDIM];   // tf32(x)
__device__ float  g_H      [(size_t)BATCH * MHALF];  // H_exp raw fp32
__device__ __half g_Hq16   [(size_t)BATCH * MHALF];  // int-valued quantized H_exp (fp16)
__device__ int    g_amax[2];

// ---------------- helpers ----------------------------------------------------
__device__ __forceinline__ float to_tf32(float x) {
    float r; asm("cvt.rna.tf32.f32 %0, %1;" : "=f"(r) : "f"(x)); return r;
}
__device__ __forceinline__ uint32_t smem_u32(const void* p) {
    uint32_t a;
    asm("{ .reg .u64 t; cvta.to.shared.u64 t, %1; cvt.u32.u64 %0, t; }" : "=r"(a) : "l"(p));
    return a;
}
__device__ __forceinline__ void cp16(uint32_t d, const void* s) {
    asm volatile("cp.async.cg.shared.global [%0], [%1], 16;" :: "r"(d), "l"(s));
}
__device__ __forceinline__ void cp_commit() {
    asm volatile("cp.async.commit_group;" ::: "memory");
}
template<int N> __device__ __forceinline__ void cp_wait() {
    asm volatile("cp.async.wait_group %0;" :: "n"(N) : "memory");
}
// dependent-FFMA delay to de-phase co-resident CTAs (no numeric effect)
__device__ __forceinline__ void desync_delay(int iters) {
    float v = 0.0f;
    #pragma unroll 1
    for (int i = 0; i < iters; i++)
        asm volatile("add.f32 %0, %0, 0f3F800000;" : "+f"(v));
}
__device__ __forceinline__ void mma_tf32(float* d, const uint32_t* a, uint32_t b0, uint32_t b1) {
    asm volatile(
        "mma.sync.aligned.m16n8k8.row.col.f32.tf32.tf32.f32 "
        "{%0,%1,%2,%3},{%4,%5,%6,%7},{%8,%9},{%0,%1,%2,%3};"
        : "+f"(d[0]), "+f"(d[1]), "+f"(d[2]), "+f"(d[3])
        : "r"(a[0]), "r"(a[1]), "r"(a[2]), "r"(a[3]), "r"(b0), "r"(b1));
}
__device__ __forceinline__ void mma_f16(float* d, const uint32_t* a, uint32_t b0, uint32_t b1) {
    asm volatile(
        "mma.sync.aligned.m16n8k16.row.col.f32.f16.f16.f32 "
        "{%0,%1,%2,%3},{%4,%5,%6,%7},{%8,%9},{%0,%1,%2,%3};"
        : "+f"(d[0]), "+f"(d[1]), "+f"(d[2]), "+f"(d[3])
        : "r"(a[0]), "r"(a[1]), "r"(a[2]), "r"(a[3]), "r"(b0), "r"(b1));
}
// D = A*B + 0  (fresh accumulator)
__device__ __forceinline__ void mma_f16_init(float* d, const uint32_t* a, uint32_t b0, uint32_t b1) {
    asm volatile(
        "mma.sync.aligned.m16n8k16.row.col.f32.f16.f16.f32 "
        "{%0,%1,%2,%3},{%4,%5,%6,%7},{%8,%9},{%10,%10,%10,%10};"
        : "=f"(d[0]), "=f"(d[1]), "=f"(d[2]), "=f"(d[3])
        : "r"(a[0]), "r"(a[1]), "r"(a[2]), "r"(a[3]), "r"(b0), "r"(b1), "f"(0.0f));
}
__device__ __forceinline__ void ldsm4(uint32_t* r, uint32_t addr) {
    asm volatile("ldmatrix.sync.aligned.m8n8.x4.shared.b16 {%0,%1,%2,%3}, [%4];"
        : "=r"(r[0]), "=r"(r[1]), "=r"(r[2]), "=r"(r[3]) : "r"(addr));
}
__device__ __forceinline__ void ldsm2(uint32_t& r0, uint32_t& r1, uint32_t addr) {
    asm volatile("ldmatrix.sync.aligned.m8n8.x2.shared.b16 {%0,%1}, [%2];"
        : "=r"(r0), "=r"(r1) : "r"(addr));
}

// ---------------- prep kernels ----------------------------------------------
__global__ void reset_kernel() { g_amax[0] = 0; g_amax[1] = 0; }

#define P1_QW 16384
#define P1_GW 16384
#define P1_AM 1024
__global__ void prep1_kernel(const float4* __restrict__ x4,
                             const float* __restrict__ W,
                             const int* __restrict__ idx,
                             const int* __restrict__ idxc) {
    int bid = blockIdx.x;
    if (bid < P1_QW) {
        int gw   = (bid * 256 + (int)threadIdx.x) >> 5;
        int lane = threadIdx.x & 31;
        int flat = gw * 32 + lane;
        int n = flat >> 12;
        int j = flat & (MHALF - 1);
        float w = W[(size_t)n * MDIM + idx[j]];

        float s = fabsf(w);
        #pragma unroll
        for (int o = 16; o; o >>= 1) s = fmaxf(s, __shfl_xor_sync(0xffffffffu, s, o));
        s = fmaxf(s, 1e-8f);

        float nb  = w / s;
        float anb = fabsf(nb);

        float v1 = anb; int i1 = lane;
        #pragma unroll
        for (int o = 16; o; o >>= 1) {
            float ov = __shfl_xor_sync(0xffffffffu, v1, o);
            int   oi = __shfl_xor_sync(0xffffffffu, i1, o);
            if (ov > v1 || (ov == v1 && oi < i1)) { v1 = ov; i1 = oi; }
        }
        float m2 = (lane == i1) ? -1.0f : anb;
        float v2 = m2; int i2 = lane;
        #pragma unroll
        for (int o = 16; o; o >>= 1) {
            float ov = __shfl_xor_sync(0xffffffffu, v2, o);
            int   oi = __shfl_xor_sync(0xffffffffu, i2, o);
            if (ov > v2 || (ov == v2 && oi < i2)) { v2 = ov; i2 = oi; }
        }
        bool top = (lane == i1) || (lane == i2);

        float q4  = rintf(nb * 7.0f) / 7.0f;
        float sgn = (nb > 0.0f) ? 1.0f : ((nb < 0.0f) ? -1.0f : 0.0f);
        float q2  = sgn * ((anb > 0.66f) ? 1.0f : (1.0f / 3.0f));
        g_Wq[flat] = (top ? q4 : q2) * s;

        float v21 = top ? 3.0f * rintf(nb * 7.0f)
                        : sgn * ((anb > 0.66f) ? 21.0f : 7.0f);
        g_Wv16[flat] = __float2half_rn(v21);
        if (lane == 0) g_sclT[(size_t)(j >> 5) * NDIM + n] = s * (1.0f / 21.0f);
    } else if (bid < P1_QW + P1_GW) {
        int t = (bid - P1_QW) * 256 + threadIdx.x;
        int n = t >> 12;
        int j = t & (MHALF - 1);
        g_Wc[t] = to_tf32(W[(size_t)n * MDIM + idxc[j]]);
    } else {
        __shared__ float sm[256];
        int lb = bid - P1_QW - P1_GW;
        const long n4 = (long)BATCH * NDIM / 4;
        float m = 0.0f;
        for (long i = (long)lb * 256 + threadIdx.x; i < n4; i += (long)P1_AM * 256) {
            float4 v = x4[i];
            m = fmaxf(m, fmaxf(fmaxf(fabsf(v.x), fabsf(v.y)), fmaxf(fabsf(v.z), fabsf(v.w))));
        }
        sm[threadIdx.x] = m;
        __syncthreads();
        #pragma unroll
        for (int s = 128; s; s >>= 1) {
            if (threadIdx.x < s) sm[threadIdx.x] = fmaxf(sm[threadIdx.x], sm[threadIdx.x + s]);
            __syncthreads();
        }
        if (threadIdx.x == 0) atomicMax(&g_amax[0], __float_as_int(sm[0]));
    }
}

#define P2_TR 4096
__global__ void prep2_kernel(const float4* __restrict__ x4) {
    int bid = blockIdx.x;
    if (bid < P2_TR) {
        __shared__ float t[32][33];
        int j0 = (bid & 127) * 32, n0 = (bid >> 7) * 32;
        int tx = threadIdx.x & 31, ty = threadIdx.x >> 5;
        #pragma unroll
        for (int s = 0; s < 32; s += 8)
            t[ty + s][tx] = g_Wq[(size_t)(n0 + ty + s) * MHALF + j0 + tx];
        __syncthreads();
        #pragma unroll
        for (int s = 0; s < 32; s += 8) {
            float v = t[tx][ty + s] * 2048.0f;
            __half h = __float2half_rn(v);
            __half l = __float2half_rn(v - __half2float(h));
            size_t o = (size_t)(j0 + ty + s) * NDIM + n0 + tx;
            g_WqThi16[o] = h;
            g_WqTlo16[o] = l;
        }
    } else {
        int t = (bid - P2_TR) * 256 + threadIdx.x;
        float sc = 127.0f / fmaxf(__int_as_float(g_amax[0]), 1e-8f);
        float4 v = x4[t];
        float q0 = fminf(fmaxf(rintf(v.x * sc), -128.0f), 127.0f);
        float q1 = fminf(fmaxf(rintf(v.y * sc), -128.0f), 127.0f);
        float q2 = fminf(fmaxf(rintf(v.z * sc), -128.0f), 127.0f);
        float q3 = fminf(fmaxf(rintf(v.w * sc), -128.0f), 127.0f);
        __half h[4] = { __float2half_rn(q0), __float2half_rn(q1),
                        __float2half_rn(q2), __float2half_rn(q3) };
        *(uint2*)&g_xq16[(size_t)t * 4] = *(uint2*)h;
        float4 c = make_float4(to_tf32(v.x), to_tf32(v.y), to_tf32(v.z), to_tf32(v.w));
        *(float4*)&g_xc[(size_t)t * 4] = c;
    }
}

// quantize H_exp -> integer-valued fp16; tail blocks fold amax_h into g_sclT
__global__ void quant_h_kernel() {
    const int NBQ = BATCH * MHALF / 4 / 256;   // 32768
    int bid = blockIdx.x;
    float ah127 = fmaxf(__int_as_float(g_amax[1]), 1e-8f);
    if (bid >= NBQ) {
        int t = (bid - NBQ) * 256 + threadIdx.x;
        float f = ah127 * (1.0f / 127.0f);
        float4 v = *(const float4*)&g_sclT[(size_t)t * 4];
        v.x *= f; v.y *= f; v.z *= f; v.w *= f;
        *(float4*)&g_sclT[(size_t)t * 4] = v;
        return;
    }
    int t = bid * 256 + threadIdx.x;
    float sh = 127.0f / ah127;
    float4 v = *(const float4*)&g_H[(size_t)t * 4];
    __half h[4];
    h[0] = __float2half_rn(fminf(fmaxf(rintf(v.x * sh), -128.0f), 127.0f));
    h[1] = __float2half_rn(fminf(fmaxf(rintf(v.y * sh), -128.0f), 127.0f));
    h[2] = __float2half_rn(fminf(fmaxf(rintf(v.z * sh), -128.0f), 127.0f));
    h[3] = __float2half_rn(fminf(fmaxf(rintf(v.w * sh), -128.0f), 127.0f));
    *(uint2*)&g_Hq16[(size_t)t * 4] = *(uint2*)h;
}

// ---------------- GEMM1 + fused symmetric SYRK (64x128 tiles, occ 2) ---------
#define NSYRK 72
__global__ void __launch_bounds__(256, 2) gemm1_kernel() {
    extern __shared__ char smem[];
    const int tid = threadIdx.x, wid = tid >> 5, lane = tid & 31;
    const int wm0 = (wid & 1) * 32, wn0 = (wid >> 1) * 32;
    const uint32_t sbase = smem_u32(smem);
    const int bid = blockIdx.x;

    const int l7 = lane & 7;
    const int lh = (lane >> 3) & 1;
    const int lq = (lane >> 4) & 1;
    uint32_t arow[2];
    #pragma unroll
    for (int i = 0; i < 2; i++)
        arow[i] = (uint32_t)((wm0 + i * 16 + l7 + 8 * lh) * 128);

    if (bid < NSYRK) {
        // ---- symmetric SYRK (tf32, K-chunk 32) ----
        int off = bid, tj = 0;
        while (off >= 2 * tj + 2) { off -= 2 * tj + 2; tj++; }
        const int ti = off;
        const int m0 = ti * 64, n0 = tj * 128;
        const int NCH = MHALF / 32;   // 128
        uint32_t brow[4];
        #pragma unroll
        for (int j = 0; j < 4; j++)
            brow[j] = (uint32_t)(8192 + (wn0 + j * 8 + l7) * 128);

        auto issue = [&](int c) {
            const int k0 = c * 32;
            const uint32_t st = sbase + (uint32_t)(c & 1) * STG1;
            #pragma unroll
            for (int p = 0; p < 2; p++) {
                int l = tid + p * 256;
                int r = l >> 3, gc = l & 7;
                cp16(st + (uint32_t)(r * 128 + ((gc ^ (r & 7)) << 4)),
                     g_Wc + (size_t)(m0 + r) * MHALF + k0 + gc * 4);
            }
            #pragma unroll
            for (int p = 0; p < 4; p++) {
                int l = tid + p * 256;
                int r = l >> 3, gc = l & 7;
                cp16(st + 8192u + (uint32_t)(r * 128 + ((gc ^ (r & 7)) << 4)),
                     g_Wc + (size_t)(n0 + r) * MHALF + k0 + gc * 4);
            }
            cp_commit();
        };
        issue(0); issue(1);

        float acc[2][4][4] = {};
        for (int c = 0; c < NCH; c++) {
            cp_wait<1>();
            __syncthreads();
            const uint32_t st = sbase + (uint32_t)(c & 1) * STG1;
            #pragma unroll
            for (int ks = 0; ks < 4; ks++) {
                uint32_t a[2][4];
                #pragma unroll
                for (int i = 0; i < 2; i++)
                    ldsm4(a[i], st + arow[i] + (uint32_t)((((ks << 1) | lq) ^ l7) << 4));
                #pragma unroll
                for (int j = 0; j < 4; j++) {
                    uint32_t b0, b1;
                    ldsm2(b0, b1, st + brow[j] + (uint32_t)((((ks << 1) | lh) ^ l7) << 4));
                    #pragma unroll
                    for (int i = 0; i < 2; i++) mma_tf32(acc[i][j], a[i], b0, b1);
                }
            }
            __syncthreads();
            if (c + 2 < NCH) issue(c + 2); else cp_commit();
        }
        const int g = lane >> 2, tig = lane & 3;
        #pragma unroll
        for (int i = 0; i < 2; i++)
            #pragma unroll
            for (int j = 0; j < 4; j++) {
                int r   = m0 + wm0 + i * 16 + g;
                int col = n0 + wn0 + j * 8 + tig * 2;
                int tjs = 2 * tj + ((wn0 + j * 8) >= 64 ? 1 : 0);
                float v0 = to_tf32(acc[i][j][0]), v1 = to_tf32(acc[i][j][1]);
                float v2 = to_tf32(acc[i][j][2]), v3 = to_tf32(acc[i][j][3]);
                if (ti <= tjs) {
                    *(float2*)&g_G[(size_t)r * NDIM + col]       = make_float2(v0, v1);
                    *(float2*)&g_G[(size_t)(r + 8) * NDIM + col] = make_float2(v2, v3);
                }
                if (ti < tjs) {
                    g_G[(size_t)col * NDIM + r]           = v0;
                    g_G[(size_t)(col + 1) * NDIM + r]     = v1;
                    g_G[(size_t)col * NDIM + r + 8]       = v2;
                    g_G[(size_t)(col + 1) * NDIM + r + 8] = v3;
                }
            }
        return;
    }

    // ---- GEMM1 path (fp16 2-term split, 64x128, K-chunk 64) ----
    // de-phase co-resident CTAs (wave-partner is ~bid+148)
    if ((bid / 148) & 1) desync_delay(400);

    const int t = bid - NSYRK;
    const int n0 = (t & 31) * 128, row0 = (t >> 5) * 64;
    const int NCH = NDIM / 64;   // 16
    uint32_t brow[4];
    #pragma unroll
    for (int j = 0; j < 4; j++)
        brow[j] = (uint32_t)(8192 + 16384 * lq + (wn0 + j * 8 + l7) * 128);

    auto issue = [&](int c) {
        const int k0 = c * 64;
        const uint32_t st = sbase + (uint32_t)(c & 1) * STG1;
        #pragma unroll
        for (int p = 0; p < 2; p++) {
            int l = tid + p * 256;
            int r = l >> 3, gc = l & 7;
            cp16(st + (uint32_t)(r * 128 + ((gc ^ (r & 7)) << 4)),
                 g_xq16 + (size_t)(row0 + r) * NDIM + k0 + gc * 8);
        }
        #pragma unroll
        for (int p = 0; p < 4; p++) {
            int l = tid + p * 256;
            int r = l >> 3, gc = l & 7;
            uint32_t d = (uint32_t)(r * 128 + ((gc ^ (r & 7)) << 4));
            cp16(st + 8192u + d,  g_WqThi16 + (size_t)(n0 + r) * NDIM + k0 + gc * 8);
            cp16(st + 24576u + d, g_WqTlo16 + (size_t)(n0 + r) * NDIM + k0 + gc * 8);
        }
        cp_commit();
    };

    issue(0); issue(1);

    float acc[2][4][4] = {};

    for (int c = 0; c < NCH; c++) {
        cp_wait<1>();
        __syncthreads();
        const uint32_t st = sbase + (uint32_t)(c & 1) * STG1;
        #pragma unroll
        for (int s = 0; s < 4; s++) {
            uint32_t a[2][4];
            #pragma unroll
            for (int i = 0; i < 2; i++)
                ldsm4(a[i], st + arow[i] + (uint32_t)((((s << 1) | lq) ^ l7) << 4));
            #pragma unroll
            for (int j = 0; j < 4; j++) {
                uint32_t b[4];
                ldsm4(b, st + brow[j] + (uint32_t)((((s << 1) | lh) ^ l7) << 4));
                #pragma unroll
                for (int i = 0; i < 2; i++) mma_f16(acc[i][j], a[i], b[0], b[1]);
                #pragma unroll
                for (int i = 0; i < 2; i++) mma_f16(acc[i][j], a[i], b[2], b[3]);
            }
        }
        __syncthreads();
        if (c + 2 < NCH) issue(c + 2); else cp_commit();
    }

    const int g = lane >> 2, tig = lane & 3;
    float lmax = 0.0f;
    const float inv = fmaxf(__int_as_float(g_amax[0]), 1e-8f) * (1.0f / (127.0f * 2048.0f));
    #pragma unroll
    for (int i = 0; i < 2; i++) {
        #pragma unroll
        for (int j = 0; j < 4; j++) {
            int r   = row0 + wm0 + i * 16 + g;
            int col = n0 + wn0 + j * 8 + tig * 2;
            float v0 = acc[i][j][0] * inv, v1 = acc[i][j][1] * inv;
            float v2 = acc[i][j][2] * inv, v3 = acc[i][j][3] * inv;
            lmax = fmaxf(lmax, fmaxf(fmaxf(fabsf(v0), fabsf(v1)),
                                     fmaxf(fabsf(v2), fabsf(v3))));
            *(float2*)&g_H[(size_t)r * MHALF + col]       = make_float2(v0, v1);
            *(float2*)&g_H[(size_t)(r + 8) * MHALF + col] = make_float2(v2, v3);
        }
    }

    float* red = (float*)smem;
    __syncthreads();
    red[tid] = lmax;
    __syncthreads();
    #pragma unroll
    for (int s = 128; s; s >>= 1) {
        if (tid < s) red[tid] = fmaxf(red[tid], red[tid + s]);
        __syncthreads();
    }
    if (tid == 0) atomicMax(&g_amax[1], __float_as_int(red[0]));
}

// ---------------- GEMM2: out = relu(Hq@Wq^T + x@G + b) -----------------------
// 64x128 tiles (occ 2), ldmatrix inner loops.
__global__ void __launch_bounds__(256, 2) gemm2_kernel(float* __restrict__ outp,
                                                       const float* __restrict__ biasp) {
    extern __shared__ char smem[];
    const int tid = threadIdx.x, wid = tid >> 5, lane = tid & 31;
    const int wm0 = (wid & 1) * 32, wn0 = (wid >> 1) * 32;
    const int n0 = blockIdx.x * 128, row0 = blockIdx.y * 64;
    const uint32_t sbase = smem_u32(smem);
    const int NCH = 64 + NDIM / 32;   // 96

    // de-phase co-resident CTAs
    {
        int bid = blockIdx.y * 8 + blockIdx.x;
        if ((bid / 148) & 1) desync_delay(400);
    }

    const int l7 = lane & 7;
    const int lh = (lane >> 3) & 1;
    const int lq = (lane >> 4) & 1;
    const int l2 = lane >> 3;
    uint32_t arow[2];
    #pragma unroll
    for (int i = 0; i < 2; i++)
        arow[i] = (uint32_t)((wm0 + i * 16 + l7 + 8 * lh) * 128);
    uint32_t brow[4];
    #pragma unroll
    for (int j = 0; j < 4; j++)
        brow[j] = (uint32_t)(8192 + (wn0 + j * 8 + l7) * 128);

    auto issue = [&](int c) {
        const uint32_t st = sbase + (uint32_t)(c & 3) * STG2;
        if (c < 64) {
            const int k0 = c * 64;
            #pragma unroll
            for (int p = 0; p < 2; p++) {
                int l = tid + p * 256;
                int r = l >> 3, gc = l & 7;
                cp16(st + (uint32_t)(r * 128 + ((gc ^ (r & 7)) << 4)),
                     g_Hq16 + (size_t)(row0 + r) * MHALF + k0 + gc * 8);
            }
            #pragma unroll
            for (int p = 0; p < 4; p++) {
                int l = tid + p * 256;
                int r = l >> 3, gc = l & 7;
                cp16(st + 8192u + (uint32_t)(r * 128 + ((gc ^ (r & 7)) << 4)),
                     g_Wv16 + (size_t)(n0 + r) * MHALF + k0 + gc * 8);
            }
            if (tid < 64) {
                int bb = tid >> 5, o = (tid & 31) * 4;
                cp16(st + 24576u + (uint32_t)(bb * 512 + o * 4),
                     g_sclT + (size_t)((k0 >> 5) + bb) * NDIM + n0 + o);
            }
        } else {
            const int k0 = (c - 64) * 32;
            #pragma unroll
            for (int p = 0; p < 2; p++) {
                int l = tid + p * 256;
                int r = l >> 3, gc = l & 7;
                cp16(st + (uint32_t)(r * 128 + ((gc ^ (r & 7)) << 4)),
                     g_xc + (size_t)(row0 + r) * NDIM + k0 + gc * 4);
            }
            #pragma unroll
            for (int p = 0; p < 4; p++) {
                int l = tid + p * 256;
                int r = l >> 3, gc = l & 7;
                cp16(st + 8192u + (uint32_t)(r * 128 + ((gc ^ (r & 7)) << 4)),
                     g_G + (size_t)(n0 + r) * NDIM + k0 + gc * 4);
            }
        }
        cp_commit();
    };

    issue(0); issue(1); issue(2);

    float accf[2][4][4] = {};

    for (int c = 0; c < NCH; c++) {
        cp_wait<2>();
        __syncthreads();
        if (c + 3 < NCH) issue(c + 3); else cp_commit();

        const uint32_t st = sbase + (uint32_t)(c & 3) * STG2;
        if (c < 64) {
            const float* sScl = (const float*)(smem + (c & 3) * STG2 + 24576);
            #pragma unroll
            for (int b32 = 0; b32 < 2; b32++) {
                uint32_t a[2][2][4];
                #pragma unroll
                for (int s16 = 0; s16 < 2; s16++)
                    #pragma unroll
                    for (int i = 0; i < 2; i++)
                        ldsm4(a[s16][i], st + arow[i] +
                              (uint32_t)(((b32 * 4 + s16 * 2 + lq) ^ l7) << 4));
                #pragma unroll
                for (int j = 0; j < 4; j++) {
                    uint32_t b[4];
                    ldsm4(b, st + brow[j] + (uint32_t)(((b32 * 4 + l2) ^ l7) << 4));
                    float acct[2][4];
                    #pragma unroll
                    for (int i = 0; i < 2; i++) mma_f16_init(acct[i], a[0][i], b[0], b[1]);
                    #pragma unroll
                    for (int i = 0; i < 2; i++) mma_f16(acct[i], a[1][i], b[2], b[3]);
                    float2 sc = *(const float2*)(sScl + b32 * 128 + wn0 + j * 8 + (lane & 3) * 2);
                    #pragma unroll
                    for (int i = 0; i < 2; i++) {
                        accf[i][j][0] += sc.x * acct[i][0];
                        accf[i][j][1] += sc.y * acct[i][1];
                        accf[i][j][2] += sc.x * acct[i][2];
                        accf[i][j][3] += sc.y * acct[i][3];
                    }
                }
            }
        } else {
            #pragma unroll
            for (int ks = 0; ks < 4; ks++) {
                uint32_t a[2][4];
                #pragma unroll
                for (int i = 0; i < 2; i++)
                    ldsm4(a[i], st + arow[i] + (uint32_t)((((ks << 1) | lq) ^ l7) << 4));
                #pragma unroll
                for (int j = 0; j < 4; j++) {
                    uint32_t b0, b1;
                    ldsm2(b0, b1, st + brow[j] + (uint32_t)((((ks << 1) | lh) ^ l7) << 4));
                    #pragma unroll
                    for (int i = 0; i < 2; i++) mma_tf32(accf[i][j], a[i], b0, b1);
                }
            }
        }
    }

    const int g = lane >> 2, tig = lane & 3;
    #pragma unroll
    for (int i = 0; i < 2; i++) {
        #pragma unroll
        for (int j = 0; j < 4; j++) {
            int r   = row0 + wm0 + i * 16 + g;
            int col = n0 + wn0 + j * 8 + tig * 2;
            float b0 = biasp[col], b1 = biasp[col + 1];
            float v0 = fmaxf(accf[i][j][0] + b0, 0.0f);
            float v1 = fmaxf(accf[i][j][1] + b1, 0.0f);
            float v2 = fmaxf(accf[i][j][2] + b0, 0.0f);
            float v3 = fmaxf(accf[i][j][3] + b1, 0.0f);
            *(float2*)&outp[(size_t)r * NDIM + col]       = make_float2(v0, v1);
            *(float2*)&outp[(size_t)(r + 8) * NDIM + col] = make_float2(v2, v3);
        }
    }
}

// ---------------- launcher ---------------------------------------------------
extern "C" void kernel_launch(void* const* d_in, const int* in_sizes, int n_in,
                              void* d_out, int out_size) {
    const float* x    = (const float*)d_in[0];
    const float* W    = (const float*)d_in[1];
    const float* b    = (const float*)d_in[2];
    const int*   idx  = (const int*)d_in[3];
    const int*   idxc = (const int*)d_in[4];
    float* out = (float*)d_out;

    const int SMEM1 = 2 * STG1;          // 80KB, occ 2
    const int SMEM2 = NSTG2 * STG2;      // 100KB, occ 2
    cudaFuncSetAttribute(gemm1_kernel, cudaFuncAttributeMaxDynamicSharedMemorySize, SMEM1);
    cudaFuncSetAttribute(gemm2_kernel, cudaFuncAttributeMaxDynamicSharedMemorySize, SMEM2);

    reset_kernel<<<1, 32>>>();
    prep1_kernel<<<P1_QW + P1_GW + P1_AM, 256>>>((const float4*)x, W, idx, idxc);
    prep2_kernel<<<P2_TR + BATCH * NDIM / 4 / 256, 256>>>((const float4*)x);

    gemm1_kernel<<<NSYRK + (MHALF / 128) * (BATCH / 64), 256, SMEM1>>>();

    quant_h_kernel<<<BATCH * MHALF / 4 / 256 + 128, 256>>>();

    gemm2_kernel<<<dim3(NDIM / 128, BATCH / 64), 256, SMEM2>>>(out, b);
}